// round 14
// baseline (speedup 1.0000x reference)
#include <cuda_runtime.h>
#include <cuda_fp16.h>

#define NN   10000
#define EE   160000
#define EEP  240000         // padded CSR capacity per dir
#define BB   8
#define HH   64
#define PART 320            // 5 slots * 64 features per (node,batch) row
#define NB   (NN*BB)        // 80000
#define VHL  (NB*PART)      // one vh layer

// ---------------- device scratch ----------------
__device__ float g_deg_out[NN];
__device__ float g_deg_in[NN];
__device__ int   g_cnt[2][NN];
__device__ int   g_off[2][NN+1];
__device__ int   g_cur[2][NN];
__device__ int   g_nbr[2][EEP];
__device__ float g_wgt[2][EEP];

__device__ __half g_vx[VHL];      // x-part slots: 0=x 1=A_f x 2=A_r x 3=cheb_f 4=cheb_r
__device__ __half g_vh[2*VHL];    // h-part slots, per layer
__device__ __half g_vr[VHL];      // (R*h)-part slots
__device__ float  g_z [NB*HH];    // Z gate (fp32)
__device__ __half g_WZR[2*128*640];  // fp16 weights, n-major [l][n][640] for Z|R gemm
__device__ __half g_WH [2*64*640];   // fp16 weights, n-major [l][n][640] for H gemm

// ---------------- helpers ----------------
struct __align__(8)  h2x2 { __half2 a, b; };
struct __align__(16) h2x4 { __half2 a, b, c, d; };

__device__ __forceinline__ float sigm(float x) { return 1.f / (1.f + __expf(-x)); }

__device__ __forceinline__ void mma_f16(float &c0, float &c1, float &c2, float &c3,
                                        unsigned a0, unsigned a1, unsigned a2, unsigned a3,
                                        unsigned b0, unsigned b1) {
    asm volatile(
        "mma.sync.aligned.m16n8k16.row.col.f32.f16.f16.f32 "
        "{%0,%1,%2,%3}, {%4,%5,%6,%7}, {%8,%9}, {%0,%1,%2,%3};"
        : "+f"(c0), "+f"(c1), "+f"(c2), "+f"(c3)
        : "r"(a0), "r"(a1), "r"(a2), "r"(a3), "r"(b0), "r"(b1));
}

__device__ __forceinline__ __half* partbuf(int id, int l) {
    return id == 0 ? g_vx : (id == 1 ? g_vh + l * VHL : g_vr);
}

// ---------------- setup ----------------
__global__ void k_zero() {
    int i = blockIdx.x * 256 + threadIdx.x;
    if (i >= NN) return;
    g_deg_out[i] = 0.f; g_deg_in[i] = 0.f;
    g_cnt[0][i] = 0;    g_cnt[1][i] = 0;
}

__global__ void k_degcnt(const float* __restrict__ ew, const int* __restrict__ ei) {
    int e = blockIdx.x * 256 + threadIdx.x;
    if (e >= EE) return;
    int s = ei[e], d = ei[EE + e];
    float w = ew[e];
    atomicAdd(&g_deg_out[s], w);
    atomicAdd(&g_deg_in[d],  w);
    atomicAdd(&g_cnt[0][d], 1);
    atomicAdd(&g_cnt[1][s], 1);
}

// scan with counts padded up to multiples of 8 (keeps segments 8-aligned)
__global__ void k_scan() {   // grid=2, block=1024
    int d = blockIdx.x;
    __shared__ int sums[1024];
    int t = threadIdx.x;
    const int CH = 10;
    int base = t * CH;
    int s = 0;
    for (int i = 0; i < CH; i++) {
        int idx = base + i;
        if (idx < NN) s += (g_cnt[d][idx] + 7) & ~7;
    }
    sums[t] = s; __syncthreads();
    for (int off = 1; off < 1024; off <<= 1) {
        int v = (t >= off) ? sums[t - off] : 0;
        __syncthreads();
        sums[t] += v;
        __syncthreads();
    }
    int run = (t == 0) ? 0 : sums[t - 1];
    for (int i = 0; i < CH; i++) {
        int idx = base + i;
        if (idx < NN) {
            g_off[d][idx] = run; g_cur[d][idx] = run;
            run += (g_cnt[d][idx] + 7) & ~7;
        }
    }
    if (t == 1023) g_off[d][NN] = run;
}

__global__ void k_fill(const float* __restrict__ ew, const int* __restrict__ ei) {
    int e = blockIdx.x * 256 + threadIdx.x;
    if (e >= EE) return;
    int s = ei[e], d = ei[EE + e];
    float w = ew[e];
    float wo = g_deg_out[s]; float nout = w / (wo > 0.f ? wo : 1.f);
    float wi = g_deg_in[d];  float nin  = w / (wi > 0.f ? wi : 1.f);
    int p = atomicAdd(&g_cur[0][d], 1); g_nbr[0][p] = s; g_wgt[0][p] = nout;
    int q = atomicAdd(&g_cur[1][s], 1); g_nbr[1][q] = d; g_wgt[1][q] = nin;
}

// fill padding slots with nbr=0, wgt=0 (exact zero contribution)
__global__ void k_pad() {
    int i = blockIdx.x * 256 + threadIdx.x;
    if (i >= 2 * NN) return;
    int d = i >= NN ? 1 : 0;
    int n = i - d * NN;
    int s = g_cur[d][n], e = g_off[d][n + 1];
    for (int j = s; j < e; j++) { g_nbr[d][j] = 0; g_wgt[d][j] = 0.f; }
}

// go -> vx slot0; hs (both layers) -> vh slot0
__global__ void k_load_acts(const float* __restrict__ go, const float* __restrict__ hs) {
    int t = blockIdx.x * 256 + threadIdx.x;
    if (t >= 3 * NB * HH) return;
    int seg = t / (NB * HH);
    int tt = t - seg * (NB * HH);
    int f = tt & 63; int rest = tt >> 6;
    int n = rest % NN; int b = rest / NN;
    int row = (n * BB + b) * PART + f;
    if (seg == 0) g_vx[row] = __float2half_rn(go[tt]);
    else          g_vh[(seg - 1) * VHL + row] = __float2half_rn(hs[(seg - 1) * NB * HH + tt]);
}

// W layout [L,2,K,128,64]. Slots: 0:(dir0+dir1,k0) 1:(0,k1) 2:(1,k1) 3:(0,k2) 4:(1,k2)
__device__ __forceinline__ float wslot(const float* W, int l, int s, int wrow, int o) {
    if (s == 0) {
        return W[((((l*2+0)*3+0)*128 + wrow)*64) + o] +
               W[((((l*2+1)*3+0)*128 + wrow)*64) + o];
    }
    int dir = (s == 1 || s == 3) ? 0 : 1;
    int k   = (s <= 2) ? 1 : 2;
    return W[((((l*2+dir)*3+k)*128 + wrow)*64) + o];
}

__global__ void k_build_wzr(const float* __restrict__ Wz, const float* __restrict__ Wr) {
    int idx = blockIdx.x * 256 + threadIdx.x;
    if (idx >= 2 * 128 * 640) return;
    int l = idx >= 128 * 640 ? 1 : 0;
    int li = idx - l * 128 * 640;
    int n = li / 640, j = li % 640;
    int p = j / 320, s = (j % 320) / 64, f = j & 63;
    int wrow = p * 64 + f;
    const float* W = (n < 64) ? Wz : Wr;
    g_WZR[l * 128 * 640 + n * 640 + j] = __float2half_rn(wslot(W, l, s, wrow, n & 63));
}

__global__ void k_build_wh(const float* __restrict__ Wh) {
    int idx = blockIdx.x * 256 + threadIdx.x;
    if (idx >= 2 * 64 * 640) return;
    int l = idx >= 64 * 640 ? 1 : 0;
    int li = idx - l * 64 * 640;
    int n = li / 640, j = li % 640;
    int p = j / 320, s = (j % 320) / 64, f = j & 63;
    g_WH[l * 64 * 640 + n * 640 + j] = __float2half_rn(wslot(Wh, l, s, p * 64 + f, n));
}

// ---------------- propagation v7: R7 geometry + padded CSR + vectorized edge loads ----------------
// grid: (NN, nbuf, 2 dirs); block 128: warp = 2 batches, 16 lanes * 4 halves = 64 feats
__global__ void __launch_bounds__(128) k_prop7(int bufA, int bufB, int lvh,
                                               int s_in_f, int s_out_f,
                                               int s_in_r, int s_out_r,
                                               int cheb, int s_prev) {
    int dir = blockIdx.z;
    __half* buf = partbuf(blockIdx.y == 0 ? bufA : bufB, lvh);
    const int*   off = g_off[dir];
    const int*   nbr = g_nbr[dir];
    const float* wgt = g_wgt[dir];
    int s_in  = dir ? s_in_r  : s_in_f;
    int s_out = dir ? s_out_r : s_out_f;
    int n    = blockIdx.x;
    int w    = threadIdx.x >> 5;
    int lane = threadIdx.x & 31;
    int b    = w * 2 + (lane >> 4);
    int fo   = (lane & 15) * 4;
    int beg = off[n], end = off[n + 1];   // 8-aligned, count multiple of 8
    int boff = b * PART + s_in * 64 + fo; // per-thread constant part of gather addr
    const int4*   nb4 = (const int4*)(nbr + beg);
    const float4* wg4 = (const float4*)(wgt + beg);
    int nb = (end - beg) >> 3;
    float4 acc = make_float4(0.f, 0.f, 0.f, 0.f);
    for (int i = 0; i < nb; i++) {
        int4   n0 = __ldg(&nb4[2 * i]);
        int4   n1 = __ldg(&nb4[2 * i + 1]);
        float4 w0 = __ldg(&wg4[2 * i]);
        float4 w1 = __ldg(&wg4[2 * i + 1]);
        {
            h2x2 v = *(const h2x2*)(buf + n0.x * (BB * PART) + boff);
            float2 f01 = __half22float2(v.a), f23 = __half22float2(v.b);
            acc.x += w0.x * f01.x; acc.y += w0.x * f01.y;
            acc.z += w0.x * f23.x; acc.w += w0.x * f23.y;
        }
        {
            h2x2 v = *(const h2x2*)(buf + n0.y * (BB * PART) + boff);
            float2 f01 = __half22float2(v.a), f23 = __half22float2(v.b);
            acc.x += w0.y * f01.x; acc.y += w0.y * f01.y;
            acc.z += w0.y * f23.x; acc.w += w0.y * f23.y;
        }
        {
            h2x2 v = *(const h2x2*)(buf + n0.z * (BB * PART) + boff);
            float2 f01 = __half22float2(v.a), f23 = __half22float2(v.b);
            acc.x += w0.z * f01.x; acc.y += w0.z * f01.y;
            acc.z += w0.z * f23.x; acc.w += w0.z * f23.y;
        }
        {
            h2x2 v = *(const h2x2*)(buf + n0.w * (BB * PART) + boff);
            float2 f01 = __half22float2(v.a), f23 = __half22float2(v.b);
            acc.x += w0.w * f01.x; acc.y += w0.w * f01.y;
            acc.z += w0.w * f23.x; acc.w += w0.w * f23.y;
        }
        {
            h2x2 v = *(const h2x2*)(buf + n1.x * (BB * PART) + boff);
            float2 f01 = __half22float2(v.a), f23 = __half22float2(v.b);
            acc.x += w1.x * f01.x; acc.y += w1.x * f01.y;
            acc.z += w1.x * f23.x; acc.w += w1.x * f23.y;
        }
        {
            h2x2 v = *(const h2x2*)(buf + n1.y * (BB * PART) + boff);
            float2 f01 = __half22float2(v.a), f23 = __half22float2(v.b);
            acc.x += w1.y * f01.x; acc.y += w1.y * f01.y;
            acc.z += w1.y * f23.x; acc.w += w1.y * f23.y;
        }
        {
            h2x2 v = *(const h2x2*)(buf + n1.z * (BB * PART) + boff);
            float2 f01 = __half22float2(v.a), f23 = __half22float2(v.b);
            acc.x += w1.z * f01.x; acc.y += w1.z * f01.y;
            acc.z += w1.z * f23.x; acc.w += w1.z * f23.y;
        }
        {
            h2x2 v = *(const h2x2*)(buf + n1.w * (BB * PART) + boff);
            float2 f01 = __half22float2(v.a), f23 = __half22float2(v.b);
            acc.x += w1.w * f01.x; acc.y += w1.w * f01.y;
            acc.z += w1.w * f23.x; acc.w += w1.w * f23.y;
        }
    }
    int orow = (n * BB + b) * PART;
    float4 res = acc;
    if (cheb) {
        h2x2 pv = *(const h2x2*)(buf + orow + s_prev * 64 + fo);
        float2 p01 = __half22float2(pv.a), p23 = __half22float2(pv.b);
        res.x = 2.f * acc.x - p01.x; res.y = 2.f * acc.y - p01.y;
        res.z = 2.f * acc.z - p23.x; res.w = 2.f * acc.w - p23.y;
    }
    h2x2 o;
    o.a = __floats2half2_rn(res.x, res.y);
    o.b = __floats2half2_rn(res.z, res.w);
    *(h2x2*)(buf + orow + s_out * 64 + fo) = o;
}

// ---------------- fp16 tensor-core GEMMs ----------------
// Z|R: [80000 x 640] @ [640 x 128]; A row = (vx row | vh row), all fp16
__global__ void __launch_bounds__(256) k_gemm_zr(int l,
                                                 const float* __restrict__ bz,
                                                 const float* __restrict__ br) {
    __shared__ __half As[128][40];
    __shared__ __half Bs[128][40];
    const __half* W = g_WZR + l * 128 * 640;
    const __half* vh = g_vh + l * VHL;
    int tid = threadIdx.x;
    int wid = tid >> 5, lane = tid & 31;
    int warpM = wid & 3, warpN = wid >> 2;
    int g4 = lane >> 2, t4 = lane & 3;
    int rowBase = blockIdx.x * 128;

    float c[2][8][4];
#pragma unroll
    for (int mt = 0; mt < 2; mt++)
#pragma unroll
        for (int nt = 0; nt < 8; nt++)
#pragma unroll
            for (int i = 0; i < 4; i++) c[mt][nt][i] = 0.f;

    for (int kk = 0; kk < 20; kk++) {
        const __half* Asrc = (kk < 10) ? g_vx : vh;
        int soff = (kk < 10 ? kk : kk - 10) * 32;
#pragma unroll
        for (int t = 0; t < 2; t++) {
            int id = tid + t * 256;
            int r = id >> 2, c8 = (id & 3) * 8;
            *(h2x4*)&As[r][c8] = *(const h2x4*)(Asrc + (rowBase + r) * PART + soff + c8);
        }
#pragma unroll
        for (int t = 0; t < 2; t++) {
            int id = tid + t * 256;
            int n = id >> 2, c8 = (id & 3) * 8;
            *(h2x4*)&Bs[n][c8] = *(const h2x4*)(W + n * 640 + kk * 32 + c8);
        }
        __syncthreads();
#pragma unroll
        for (int kc = 0; kc < 2; kc++) {
            int k0 = kc * 16;
            int kA = k0 + 2 * t4;
            unsigned a[2][4];
#pragma unroll
            for (int mt = 0; mt < 2; mt++) {
                int rm = warpM * 32 + mt * 16;
                a[mt][0] = *(const unsigned*)&As[rm + g4][kA];
                a[mt][1] = *(const unsigned*)&As[rm + g4 + 8][kA];
                a[mt][2] = *(const unsigned*)&As[rm + g4][kA + 8];
                a[mt][3] = *(const unsigned*)&As[rm + g4 + 8][kA + 8];
            }
#pragma unroll
            for (int nt = 0; nt < 8; nt++) {
                int cn = warpN * 64 + nt * 8;
                unsigned b0 = *(const unsigned*)&Bs[cn + g4][kA];
                unsigned b1 = *(const unsigned*)&Bs[cn + g4][kA + 8];
#pragma unroll
                for (int mt = 0; mt < 2; mt++)
                    mma_f16(c[mt][nt][0], c[mt][nt][1], c[mt][nt][2], c[mt][nt][3],
                            a[mt][0], a[mt][1], a[mt][2], a[mt][3], b0, b1);
            }
        }
        __syncthreads();
    }

#pragma unroll
    for (int mt = 0; mt < 2; mt++) {
#pragma unroll
        for (int nt = 0; nt < 8; nt++) {
            int gr0 = rowBase + warpM * 32 + mt * 16 + g4;
            int cv  = nt * 8 + 2 * t4;
            if (warpN == 0) {
                float bz0 = __ldg(&bz[cv]), bz1 = __ldg(&bz[cv + 1]);
                g_z[gr0 * HH + cv]           = sigm(c[mt][nt][0] + bz0);
                g_z[gr0 * HH + cv + 1]       = sigm(c[mt][nt][1] + bz1);
                g_z[(gr0 + 8) * HH + cv]     = sigm(c[mt][nt][2] + bz0);
                g_z[(gr0 + 8) * HH + cv + 1] = sigm(c[mt][nt][3] + bz1);
            } else {
                float br0 = __ldg(&br[cv]), br1 = __ldg(&br[cv + 1]);
                float h00 = __half2float(vh[gr0 * PART + cv]);
                float h01 = __half2float(vh[gr0 * PART + cv + 1]);
                float h10 = __half2float(vh[(gr0 + 8) * PART + cv]);
                float h11 = __half2float(vh[(gr0 + 8) * PART + cv + 1]);
                g_vr[gr0 * PART + cv]           = __float2half_rn(sigm(c[mt][nt][0] + br0) * h00);
                g_vr[gr0 * PART + cv + 1]       = __float2half_rn(sigm(c[mt][nt][1] + br1) * h01);
                g_vr[(gr0 + 8) * PART + cv]     = __float2half_rn(sigm(c[mt][nt][2] + br0) * h10);
                g_vr[(gr0 + 8) * PART + cv + 1] = __float2half_rn(sigm(c[mt][nt][3] + br1) * h11);
            }
        }
    }
}

// H: [80000 x 640] @ [640 x 64]; A row = (vx row | vr row). GRU update -> vx slot0
__global__ void __launch_bounds__(256) k_gemm_h(int l, const float* __restrict__ bh) {
    __shared__ __half As[128][40];
    __shared__ __half Bs[64][40];
    const __half* W = g_WH + l * 64 * 640;
    const __half* vh = g_vh + l * VHL;
    int tid = threadIdx.x;
    int wid = tid >> 5, lane = tid & 31;
    int g4 = lane >> 2, t4 = lane & 3;
    int rowBase = blockIdx.x * 128;

    float c[8][4];
#pragma unroll
    for (int nt = 0; nt < 8; nt++)
#pragma unroll
        for (int i = 0; i < 4; i++) c[nt][i] = 0.f;

    for (int kk = 0; kk < 20; kk++) {
        const __half* Asrc = (kk < 10) ? g_vx : g_vr;
        int soff = (kk < 10 ? kk : kk - 10) * 32;
#pragma unroll
        for (int t = 0; t < 2; t++) {
            int id = tid + t * 256;
            int r = id >> 2, c8 = (id & 3) * 8;
            *(h2x4*)&As[r][c8] = *(const h2x4*)(Asrc + (rowBase + r) * PART + soff + c8);
        }
        {
            int n = tid >> 2, c8 = (tid & 3) * 8;
            *(h2x4*)&Bs[n][c8] = *(const h2x4*)(W + n * 640 + kk * 32 + c8);
        }
        __syncthreads();
#pragma unroll
        for (int kc = 0; kc < 2; kc++) {
            int kA = kc * 16 + 2 * t4;
            int rm = wid * 16;
            unsigned a0 = *(const unsigned*)&As[rm + g4][kA];
            unsigned a1 = *(const unsigned*)&As[rm + g4 + 8][kA];
            unsigned a2 = *(const unsigned*)&As[rm + g4][kA + 8];
            unsigned a3 = *(const unsigned*)&As[rm + g4 + 8][kA + 8];
#pragma unroll
            for (int nt = 0; nt < 8; nt++) {
                unsigned b0 = *(const unsigned*)&Bs[nt * 8 + g4][kA];
                unsigned b1 = *(const unsigned*)&Bs[nt * 8 + g4][kA + 8];
                mma_f16(c[nt][0], c[nt][1], c[nt][2], c[nt][3], a0, a1, a2, a3, b0, b1);
            }
        }
        __syncthreads();
    }

#pragma unroll
    for (int nt = 0; nt < 8; nt++) {
        int gr0 = rowBase + wid * 16 + g4;
        int cv  = nt * 8 + 2 * t4;
        float bh0 = __ldg(&bh[cv]), bh1 = __ldg(&bh[cv + 1]);
#pragma unroll
        for (int half_i = 0; half_i < 2; half_i++) {
            int gr = gr0 + half_i * 8;
            float ht0 = tanhf(c[nt][half_i * 2 + 0] + bh0);
            float ht1 = tanhf(c[nt][half_i * 2 + 1] + bh1);
            float z0 = g_z[gr * HH + cv], z1 = g_z[gr * HH + cv + 1];
            float h0 = __half2float(vh[gr * PART + cv]);
            float h1 = __half2float(vh[gr * PART + cv + 1]);
            g_vx[gr * PART + cv]     = __float2half_rn(z0 * h0 + (1.f - z0) * ht0);
            g_vx[gr * PART + cv + 1] = __float2half_rn(z1 * h1 + (1.f - z1) * ht1);
        }
    }
}

// ---------------- projection ----------------
__global__ void __launch_bounds__(256) k_proj(const float* __restrict__ pw,
                                              const float* __restrict__ pb,
                                              float* __restrict__ out) {
    __shared__ float Ws[64 * 32];
    __shared__ float Bsh[32];
    int tid = threadIdx.x;
    for (int i = tid; i < 64 * 32; i += 256) Ws[i] = pw[i];
    if (tid < 32) Bsh[tid] = pb[tid];
    __syncthreads();
    int w = tid >> 5, lane = tid & 31;
    int g = blockIdx.x * 8 + w;
    const __half* x = g_vx + g * PART;
    float xv0 = __half2float(x[lane]);
    float xv1 = __half2float(x[32 + lane]);
    float acc = Bsh[lane];
#pragma unroll
    for (int f = 0; f < 32; f++)
        acc += __shfl_sync(0xffffffffu, xv0, f) * Ws[f * 32 + lane];
#pragma unroll
    for (int f = 0; f < 32; f++)
        acc += __shfl_sync(0xffffffffu, xv1, f) * Ws[(32 + f) * 32 + lane];
    int n = g >> 3, b = g & 7;
    out[(b * NN + n) * 32 + lane] = acc;
}

// ---------------- launch ----------------
extern "C" void kernel_launch(void* const* d_in, const int* in_sizes, int n_in,
                              void* d_out, int out_size) {
    (void)in_sizes; (void)n_in; (void)out_size;
    const float* ew = (const float*)d_in[0];
    const float* hs = (const float*)d_in[1];
    const float* go = (const float*)d_in[2];
    const float* Wz = (const float*)d_in[3];
    const float* bz = (const float*)d_in[4];
    const float* Wr = (const float*)d_in[5];
    const float* br = (const float*)d_in[6];
    const float* Wh = (const float*)d_in[7];
    const float* bh = (const float*)d_in[8];
    const float* pw = (const float*)d_in[9];
    const float* pb = (const float*)d_in[10];
    const int*   ei = (const int*)d_in[11];
    float* out = (float*)d_out;

    dim3 g2(NN, 2, 2), g1(NN, 1, 2);

    // launch 1-3: setup that the sacrificial gemm needs
    k_zero<<<(NN + 255) / 256, 256>>>();
    k_load_acts<<<(3 * NB * HH + 255) / 256, 256>>>(go, hs);
    k_build_wzr<<<(2 * 128 * 640 + 255) / 256, 256>>>(Wz, Wr);
    // launch 4: SACRIFICIAL gemm — lands in the ncu capture window.
    // Reads vx/vh (zero-init or stale), writes g_z / g_vr which the real
    // layer-0 gemm below fully overwrites => final output unaffected.
    k_gemm_zr<<<625, 256>>>(0, bz, br);
    // real CSR build
    k_degcnt<<<(EE + 255) / 256, 256>>>(ew, ei);
    k_scan<<<2, 1024>>>();
    k_fill<<<(EE + 255) / 256, 256>>>(ew, ei);
    k_pad<<<(2 * NN + 255) / 256, 256>>>();
    k_build_wh<<<(2 * 64 * 640 + 255) / 256, 256>>>(Wh);

    for (int l = 0; l < 2; l++) {
        k_prop7<<<g2, 128>>>(0, 1, l, 0, 1, 0, 2, 0, 0);   // slot1 = A_f s0; slot2 = A_r s0
        k_prop7<<<g2, 128>>>(0, 1, l, 1, 3, 2, 4, 1, 0);   // slot3/4 = 2 A(slot1/2) - s0

        k_gemm_zr<<<625, 256>>>(l, bz + l * HH, br + l * HH);

        k_prop7<<<g1, 128>>>(2, 2, l, 0, 1, 0, 2, 0, 0);
        k_prop7<<<g1, 128>>>(2, 2, l, 1, 3, 2, 4, 1, 0);

        k_gemm_h<<<625, 256>>>(l, bh + l * HH);            // -> new h in vx slot0
    }

    k_proj<<<NB / 8, 256>>>(pw, pb, out);
}

// round 15
// speedup vs baseline: 1.3345x; 1.3345x over previous
#include <cuda_runtime.h>
#include <cuda_fp16.h>

#define NN   10000
#define EE   160000
#define EEP  240000         // padded CSR capacity per dir
#define BB   8
#define HH   64
#define PART 320            // 5 slots * 64 features per (node,batch) row
#define NB   (NN*BB)        // 80000
#define VHL  (NB*PART)      // one vh layer

// ---------------- device scratch ----------------
__device__ float g_deg_out[NN];
__device__ float g_deg_in[NN];
__device__ int   g_cnt[2][NN];
__device__ int   g_off[2][NN+1];
__device__ int   g_cur[2][NN];
__device__ int   g_nbr[2][EEP];
__device__ float g_wgt[2][EEP];

__device__ __half g_vx[VHL];      // x-part slots: 0=x 1=A_f x 2=A_r x 3=cheb_f 4=cheb_r
__device__ __half g_vh[2*VHL];    // h-part slots, per layer
__device__ __half g_vr[VHL];      // (R*h)-part slots
__device__ float  g_z [NB*HH];    // Z gate (fp32)
__device__ __half g_WZR[2*128*640];  // fp16 weights, n-major [l][n][640] for Z|R gemm
__device__ __half g_WH [2*64*640];   // fp16 weights, n-major [l][n][640] for H gemm

// ---------------- helpers ----------------
struct __align__(8)  h2x2 { __half2 a, b; };
struct __align__(16) h2x4 { __half2 a, b, c, d; };

__device__ __forceinline__ float sigm(float x) { return 1.f / (1.f + __expf(-x)); }

__device__ __forceinline__ void mma_f16(float &c0, float &c1, float &c2, float &c3,
                                        unsigned a0, unsigned a1, unsigned a2, unsigned a3,
                                        unsigned b0, unsigned b1) {
    asm volatile(
        "mma.sync.aligned.m16n8k16.row.col.f32.f16.f16.f32 "
        "{%0,%1,%2,%3}, {%4,%5,%6,%7}, {%8,%9}, {%0,%1,%2,%3};"
        : "+f"(c0), "+f"(c1), "+f"(c2), "+f"(c3)
        : "r"(a0), "r"(a1), "r"(a2), "r"(a3), "r"(b0), "r"(b1));
}

__device__ __forceinline__ unsigned smem_u32(const void* p) {
    return (unsigned)__cvta_generic_to_shared(p);
}
__device__ __forceinline__ void cp16(unsigned dst, const void* src) {
    asm volatile("cp.async.cg.shared.global [%0], [%1], 16;" :: "r"(dst), "l"(src));
}
__device__ __forceinline__ void cp_commit() {
    asm volatile("cp.async.commit_group;");
}
template<int N> __device__ __forceinline__ void cp_wait() {
    asm volatile("cp.async.wait_group %0;" :: "n"(N));
}

__device__ __forceinline__ __half* partbuf(int id, int l) {
    return id == 0 ? g_vx : (id == 1 ? g_vh + l * VHL : g_vr);
}

// ---------------- setup ----------------
__global__ void k_zero() {
    int i = blockIdx.x * 256 + threadIdx.x;
    if (i >= NN) return;
    g_deg_out[i] = 0.f; g_deg_in[i] = 0.f;
    g_cnt[0][i] = 0;    g_cnt[1][i] = 0;
}

__global__ void k_degcnt(const float* __restrict__ ew, const int* __restrict__ ei) {
    int e = blockIdx.x * 256 + threadIdx.x;
    if (e >= EE) return;
    int s = ei[e], d = ei[EE + e];
    float w = ew[e];
    atomicAdd(&g_deg_out[s], w);
    atomicAdd(&g_deg_in[d],  w);
    atomicAdd(&g_cnt[0][d], 1);
    atomicAdd(&g_cnt[1][s], 1);
}

// scan with counts padded up to multiples of 8 (keeps segments 8-aligned)
__global__ void k_scan() {   // grid=2, block=1024
    int d = blockIdx.x;
    __shared__ int sums[1024];
    int t = threadIdx.x;
    const int CH = 10;
    int base = t * CH;
    int s = 0;
    for (int i = 0; i < CH; i++) {
        int idx = base + i;
        if (idx < NN) s += (g_cnt[d][idx] + 7) & ~7;
    }
    sums[t] = s; __syncthreads();
    for (int off = 1; off < 1024; off <<= 1) {
        int v = (t >= off) ? sums[t - off] : 0;
        __syncthreads();
        sums[t] += v;
        __syncthreads();
    }
    int run = (t == 0) ? 0 : sums[t - 1];
    for (int i = 0; i < CH; i++) {
        int idx = base + i;
        if (idx < NN) {
            g_off[d][idx] = run; g_cur[d][idx] = run;
            run += (g_cnt[d][idx] + 7) & ~7;
        }
    }
    if (t == 1023) g_off[d][NN] = run;
}

__global__ void k_fill(const float* __restrict__ ew, const int* __restrict__ ei) {
    int e = blockIdx.x * 256 + threadIdx.x;
    if (e >= EE) return;
    int s = ei[e], d = ei[EE + e];
    float w = ew[e];
    float wo = g_deg_out[s]; float nout = w / (wo > 0.f ? wo : 1.f);
    float wi = g_deg_in[d];  float nin  = w / (wi > 0.f ? wi : 1.f);
    int p = atomicAdd(&g_cur[0][d], 1); g_nbr[0][p] = s; g_wgt[0][p] = nout;
    int q = atomicAdd(&g_cur[1][s], 1); g_nbr[1][q] = d; g_wgt[1][q] = nin;
}

// fill padding slots with nbr=0, wgt=0 (exact zero contribution)
__global__ void k_pad() {
    int i = blockIdx.x * 256 + threadIdx.x;
    if (i >= 2 * NN) return;
    int d = i >= NN ? 1 : 0;
    int n = i - d * NN;
    int s = g_cur[d][n], e = g_off[d][n + 1];
    for (int j = s; j < e; j++) { g_nbr[d][j] = 0; g_wgt[d][j] = 0.f; }
}

// go -> vx slot0; hs (both layers) -> vh slot0
__global__ void k_load_acts(const float* __restrict__ go, const float* __restrict__ hs) {
    int t = blockIdx.x * 256 + threadIdx.x;
    if (t >= 3 * NB * HH) return;
    int seg = t / (NB * HH);
    int tt = t - seg * (NB * HH);
    int f = tt & 63; int rest = tt >> 6;
    int n = rest % NN; int b = rest / NN;
    int row = (n * BB + b) * PART + f;
    if (seg == 0) g_vx[row] = __float2half_rn(go[tt]);
    else          g_vh[(seg - 1) * VHL + row] = __float2half_rn(hs[(seg - 1) * NB * HH + tt]);
}

// W layout [L,2,K,128,64]. Slots: 0:(dir0+dir1,k0) 1:(0,k1) 2:(1,k1) 3:(0,k2) 4:(1,k2)
__device__ __forceinline__ float wslot(const float* W, int l, int s, int wrow, int o) {
    if (s == 0) {
        return W[((((l*2+0)*3+0)*128 + wrow)*64) + o] +
               W[((((l*2+1)*3+0)*128 + wrow)*64) + o];
    }
    int dir = (s == 1 || s == 3) ? 0 : 1;
    int k   = (s <= 2) ? 1 : 2;
    return W[((((l*2+dir)*3+k)*128 + wrow)*64) + o];
}

__global__ void k_build_wzr(const float* __restrict__ Wz, const float* __restrict__ Wr) {
    int idx = blockIdx.x * 256 + threadIdx.x;
    if (idx >= 2 * 128 * 640) return;
    int l = idx >= 128 * 640 ? 1 : 0;
    int li = idx - l * 128 * 640;
    int n = li / 640, j = li % 640;
    int p = j / 320, s = (j % 320) / 64, f = j & 63;
    int wrow = p * 64 + f;
    const float* W = (n < 64) ? Wz : Wr;
    g_WZR[l * 128 * 640 + n * 640 + j] = __float2half_rn(wslot(W, l, s, wrow, n & 63));
}

__global__ void k_build_wh(const float* __restrict__ Wh) {
    int idx = blockIdx.x * 256 + threadIdx.x;
    if (idx >= 2 * 64 * 640) return;
    int l = idx >= 64 * 640 ? 1 : 0;
    int li = idx - l * 64 * 640;
    int n = li / 640, j = li % 640;
    int p = j / 320, s = (j % 320) / 64, f = j & 63;
    g_WH[l * 64 * 640 + n * 640 + j] = __float2half_rn(wslot(Wh, l, s, p * 64 + f, n));
}

// ---------------- propagation v7: padded CSR + vectorized edge loads ----------------
// grid: (NN, nbuf, 2 dirs); block 128: warp = 2 batches, 16 lanes * 4 halves = 64 feats
__global__ void __launch_bounds__(128) k_prop7(int bufA, int bufB, int lvh,
                                               int s_in_f, int s_out_f,
                                               int s_in_r, int s_out_r,
                                               int cheb, int s_prev) {
    int dir = blockIdx.z;
    __half* buf = partbuf(blockIdx.y == 0 ? bufA : bufB, lvh);
    const int*   off = g_off[dir];
    const int*   nbr = g_nbr[dir];
    const float* wgt = g_wgt[dir];
    int s_in  = dir ? s_in_r  : s_in_f;
    int s_out = dir ? s_out_r : s_out_f;
    int n    = blockIdx.x;
    int w    = threadIdx.x >> 5;
    int lane = threadIdx.x & 31;
    int b    = w * 2 + (lane >> 4);
    int fo   = (lane & 15) * 4;
    int beg = off[n], end = off[n + 1];   // 8-aligned, count multiple of 8
    int boff = b * PART + s_in * 64 + fo;
    const int4*   nb4 = (const int4*)(nbr + beg);
    const float4* wg4 = (const float4*)(wgt + beg);
    int nb = (end - beg) >> 3;
    float4 acc = make_float4(0.f, 0.f, 0.f, 0.f);
    for (int i = 0; i < nb; i++) {
        int4   n0 = __ldg(&nb4[2 * i]);
        int4   n1 = __ldg(&nb4[2 * i + 1]);
        float4 w0 = __ldg(&wg4[2 * i]);
        float4 w1 = __ldg(&wg4[2 * i + 1]);
        {
            h2x2 v = *(const h2x2*)(buf + n0.x * (BB * PART) + boff);
            float2 f01 = __half22float2(v.a), f23 = __half22float2(v.b);
            acc.x += w0.x * f01.x; acc.y += w0.x * f01.y;
            acc.z += w0.x * f23.x; acc.w += w0.x * f23.y;
        }
        {
            h2x2 v = *(const h2x2*)(buf + n0.y * (BB * PART) + boff);
            float2 f01 = __half22float2(v.a), f23 = __half22float2(v.b);
            acc.x += w0.y * f01.x; acc.y += w0.y * f01.y;
            acc.z += w0.y * f23.x; acc.w += w0.y * f23.y;
        }
        {
            h2x2 v = *(const h2x2*)(buf + n0.z * (BB * PART) + boff);
            float2 f01 = __half22float2(v.a), f23 = __half22float2(v.b);
            acc.x += w0.z * f01.x; acc.y += w0.z * f01.y;
            acc.z += w0.z * f23.x; acc.w += w0.z * f23.y;
        }
        {
            h2x2 v = *(const h2x2*)(buf + n0.w * (BB * PART) + boff);
            float2 f01 = __half22float2(v.a), f23 = __half22float2(v.b);
            acc.x += w0.w * f01.x; acc.y += w0.w * f01.y;
            acc.z += w0.w * f23.x; acc.w += w0.w * f23.y;
        }
        {
            h2x2 v = *(const h2x2*)(buf + n1.x * (BB * PART) + boff);
            float2 f01 = __half22float2(v.a), f23 = __half22float2(v.b);
            acc.x += w1.x * f01.x; acc.y += w1.x * f01.y;
            acc.z += w1.x * f23.x; acc.w += w1.x * f23.y;
        }
        {
            h2x2 v = *(const h2x2*)(buf + n1.y * (BB * PART) + boff);
            float2 f01 = __half22float2(v.a), f23 = __half22float2(v.b);
            acc.x += w1.y * f01.x; acc.y += w1.y * f01.y;
            acc.z += w1.y * f23.x; acc.w += w1.y * f23.y;
        }
        {
            h2x2 v = *(const h2x2*)(buf + n1.z * (BB * PART) + boff);
            float2 f01 = __half22float2(v.a), f23 = __half22float2(v.b);
            acc.x += w1.z * f01.x; acc.y += w1.z * f01.y;
            acc.z += w1.z * f23.x; acc.w += w1.z * f23.y;
        }
        {
            h2x2 v = *(const h2x2*)(buf + n1.w * (BB * PART) + boff);
            float2 f01 = __half22float2(v.a), f23 = __half22float2(v.b);
            acc.x += w1.w * f01.x; acc.y += w1.w * f01.y;
            acc.z += w1.w * f23.x; acc.w += w1.w * f23.y;
        }
    }
    int orow = (n * BB + b) * PART;
    float4 res = acc;
    if (cheb) {
        h2x2 pv = *(const h2x2*)(buf + orow + s_prev * 64 + fo);
        float2 p01 = __half22float2(pv.a), p23 = __half22float2(pv.b);
        res.x = 2.f * acc.x - p01.x; res.y = 2.f * acc.y - p01.y;
        res.z = 2.f * acc.z - p23.x; res.w = 2.f * acc.w - p23.y;
    }
    h2x2 o;
    o.a = __floats2half2_rn(res.x, res.y);
    o.b = __floats2half2_rn(res.z, res.w);
    *(h2x2*)(buf + orow + s_out * 64 + fo) = o;
}

// ---------------- fp16 tensor-core GEMMs (cp.async double-buffered) ----------------
// Z|R: [80000 x 640] @ [640 x 128]; A row = (vx row | vh row), all fp16
__global__ void __launch_bounds__(256) k_gemm_zr(int l,
                                                 const float* __restrict__ bz,
                                                 const float* __restrict__ br) {
    __shared__ __align__(16) __half As[2][128][40];
    __shared__ __align__(16) __half Bs[2][128][40];
    const __half* W = g_WZR + l * 128 * 640;
    const __half* vh = g_vh + l * VHL;
    int tid = threadIdx.x;
    int wid = tid >> 5, lane = tid & 31;
    int warpM = wid & 3, warpN = wid >> 2;
    int g4 = lane >> 2, t4 = lane & 3;
    int rowBase = blockIdx.x * 128;

    float c[2][8][4];
#pragma unroll
    for (int mt = 0; mt < 2; mt++)
#pragma unroll
        for (int nt = 0; nt < 8; nt++)
#pragma unroll
            for (int i = 0; i < 4; i++) c[mt][nt][i] = 0.f;

    auto issue = [&](int kk, int buf) {
        const __half* Asrc = (kk < 10) ? g_vx : vh;
        int soff = (kk < 10 ? kk : kk - 10) * 32;
#pragma unroll
        for (int t = 0; t < 2; t++) {
            int id = tid + t * 256;
            int r = id >> 2, c8 = (id & 3) * 8;
            cp16(smem_u32(&As[buf][r][c8]),
                 Asrc + (rowBase + r) * PART + soff + c8);
        }
#pragma unroll
        for (int t = 0; t < 2; t++) {
            int id = tid + t * 256;
            int n = id >> 2, c8 = (id & 3) * 8;
            cp16(smem_u32(&Bs[buf][n][c8]), W + n * 640 + kk * 32 + c8);
        }
        cp_commit();
    };

    issue(0, 0);
    for (int kk = 0; kk < 20; kk++) {
        int buf = kk & 1;
        if (kk < 19) { issue(kk + 1, buf ^ 1); cp_wait<1>(); }
        else         { cp_wait<0>(); }
        __syncthreads();
#pragma unroll
        for (int kc = 0; kc < 2; kc++) {
            int kA = kc * 16 + 2 * t4;
            unsigned a[2][4];
#pragma unroll
            for (int mt = 0; mt < 2; mt++) {
                int rm = warpM * 32 + mt * 16;
                a[mt][0] = *(const unsigned*)&As[buf][rm + g4][kA];
                a[mt][1] = *(const unsigned*)&As[buf][rm + g4 + 8][kA];
                a[mt][2] = *(const unsigned*)&As[buf][rm + g4][kA + 8];
                a[mt][3] = *(const unsigned*)&As[buf][rm + g4 + 8][kA + 8];
            }
#pragma unroll
            for (int nt = 0; nt < 8; nt++) {
                int cn = warpN * 64 + nt * 8;
                unsigned b0 = *(const unsigned*)&Bs[buf][cn + g4][kA];
                unsigned b1 = *(const unsigned*)&Bs[buf][cn + g4][kA + 8];
#pragma unroll
                for (int mt = 0; mt < 2; mt++)
                    mma_f16(c[mt][nt][0], c[mt][nt][1], c[mt][nt][2], c[mt][nt][3],
                            a[mt][0], a[mt][1], a[mt][2], a[mt][3], b0, b1);
            }
        }
        __syncthreads();
    }

#pragma unroll
    for (int mt = 0; mt < 2; mt++) {
#pragma unroll
        for (int nt = 0; nt < 8; nt++) {
            int gr0 = rowBase + warpM * 32 + mt * 16 + g4;
            int cv  = nt * 8 + 2 * t4;
            if (warpN == 0) {
                float bz0 = __ldg(&bz[cv]), bz1 = __ldg(&bz[cv + 1]);
                g_z[gr0 * HH + cv]           = sigm(c[mt][nt][0] + bz0);
                g_z[gr0 * HH + cv + 1]       = sigm(c[mt][nt][1] + bz1);
                g_z[(gr0 + 8) * HH + cv]     = sigm(c[mt][nt][2] + bz0);
                g_z[(gr0 + 8) * HH + cv + 1] = sigm(c[mt][nt][3] + bz1);
            } else {
                float br0 = __ldg(&br[cv]), br1 = __ldg(&br[cv + 1]);
                float h00 = __half2float(vh[gr0 * PART + cv]);
                float h01 = __half2float(vh[gr0 * PART + cv + 1]);
                float h10 = __half2float(vh[(gr0 + 8) * PART + cv]);
                float h11 = __half2float(vh[(gr0 + 8) * PART + cv + 1]);
                g_vr[gr0 * PART + cv]           = __float2half_rn(sigm(c[mt][nt][0] + br0) * h00);
                g_vr[gr0 * PART + cv + 1]       = __float2half_rn(sigm(c[mt][nt][1] + br1) * h01);
                g_vr[(gr0 + 8) * PART + cv]     = __float2half_rn(sigm(c[mt][nt][2] + br0) * h10);
                g_vr[(gr0 + 8) * PART + cv + 1] = __float2half_rn(sigm(c[mt][nt][3] + br1) * h11);
            }
        }
    }
}

// H: [80000 x 640] @ [640 x 64]; A row = (vx row | vr row). GRU update -> vx slot0
__global__ void __launch_bounds__(256) k_gemm_h(int l, const float* __restrict__ bh) {
    __shared__ __align__(16) __half As[2][128][40];
    __shared__ __align__(16) __half Bs[2][64][40];
    const __half* W = g_WH + l * 64 * 640;
    const __half* vh = g_vh + l * VHL;
    int tid = threadIdx.x;
    int wid = tid >> 5, lane = tid & 31;
    int g4 = lane >> 2, t4 = lane & 3;
    int rowBase = blockIdx.x * 128;

    float c[8][4];
#pragma unroll
    for (int nt = 0; nt < 8; nt++)
#pragma unroll
        for (int i = 0; i < 4; i++) c[nt][i] = 0.f;

    auto issue = [&](int kk, int buf) {
        const __half* Asrc = (kk < 10) ? g_vx : g_vr;
        int soff = (kk < 10 ? kk : kk - 10) * 32;
#pragma unroll
        for (int t = 0; t < 2; t++) {
            int id = tid + t * 256;
            int r = id >> 2, c8 = (id & 3) * 8;
            cp16(smem_u32(&As[buf][r][c8]),
                 Asrc + (rowBase + r) * PART + soff + c8);
        }
        {
            int n = tid >> 2, c8 = (tid & 3) * 8;
            cp16(smem_u32(&Bs[buf][n][c8]), W + n * 640 + kk * 32 + c8);
        }
        cp_commit();
    };

    issue(0, 0);
    for (int kk = 0; kk < 20; kk++) {
        int buf = kk & 1;
        if (kk < 19) { issue(kk + 1, buf ^ 1); cp_wait<1>(); }
        else         { cp_wait<0>(); }
        __syncthreads();
#pragma unroll
        for (int kc = 0; kc < 2; kc++) {
            int kA = kc * 16 + 2 * t4;
            int rm = wid * 16;
            unsigned a0 = *(const unsigned*)&As[buf][rm + g4][kA];
            unsigned a1 = *(const unsigned*)&As[buf][rm + g4 + 8][kA];
            unsigned a2 = *(const unsigned*)&As[buf][rm + g4][kA + 8];
            unsigned a3 = *(const unsigned*)&As[buf][rm + g4 + 8][kA + 8];
#pragma unroll
            for (int nt = 0; nt < 8; nt++) {
                unsigned b0 = *(const unsigned*)&Bs[buf][nt * 8 + g4][kA];
                unsigned b1 = *(const unsigned*)&Bs[buf][nt * 8 + g4][kA + 8];
                mma_f16(c[nt][0], c[nt][1], c[nt][2], c[nt][3], a0, a1, a2, a3, b0, b1);
            }
        }
        __syncthreads();
    }

#pragma unroll
    for (int nt = 0; nt < 8; nt++) {
        int gr0 = rowBase + wid * 16 + g4;
        int cv  = nt * 8 + 2 * t4;
        float bh0 = __ldg(&bh[cv]), bh1 = __ldg(&bh[cv + 1]);
#pragma unroll
        for (int half_i = 0; half_i < 2; half_i++) {
            int gr = gr0 + half_i * 8;
            float ht0 = tanhf(c[nt][half_i * 2 + 0] + bh0);
            float ht1 = tanhf(c[nt][half_i * 2 + 1] + bh1);
            float z0 = g_z[gr * HH + cv], z1 = g_z[gr * HH + cv + 1];
            float h0 = __half2float(vh[gr * PART + cv]);
            float h1 = __half2float(vh[gr * PART + cv + 1]);
            g_vx[gr * PART + cv]     = __float2half_rn(z0 * h0 + (1.f - z0) * ht0);
            g_vx[gr * PART + cv + 1] = __float2half_rn(z1 * h1 + (1.f - z1) * ht1);
        }
    }
}

// ---------------- projection ----------------
__global__ void __launch_bounds__(256) k_proj(const float* __restrict__ pw,
                                              const float* __restrict__ pb,
                                              float* __restrict__ out) {
    __shared__ float Ws[64 * 32];
    __shared__ float Bsh[32];
    int tid = threadIdx.x;
    for (int i = tid; i < 64 * 32; i += 256) Ws[i] = pw[i];
    if (tid < 32) Bsh[tid] = pb[tid];
    __syncthreads();
    int w = tid >> 5, lane = tid & 31;
    int g = blockIdx.x * 8 + w;
    const __half* x = g_vx + g * PART;
    float xv0 = __half2float(x[lane]);
    float xv1 = __half2float(x[32 + lane]);
    float acc = Bsh[lane];
#pragma unroll
    for (int f = 0; f < 32; f++)
        acc += __shfl_sync(0xffffffffu, xv0, f) * Ws[f * 32 + lane];
#pragma unroll
    for (int f = 0; f < 32; f++)
        acc += __shfl_sync(0xffffffffu, xv1, f) * Ws[(32 + f) * 32 + lane];
    int n = g >> 3, b = g & 7;
    out[(b * NN + n) * 32 + lane] = acc;
}

// ---------------- launch ----------------
extern "C" void kernel_launch(void* const* d_in, const int* in_sizes, int n_in,
                              void* d_out, int out_size) {
    (void)in_sizes; (void)n_in; (void)out_size;
    const float* ew = (const float*)d_in[0];
    const float* hs = (const float*)d_in[1];
    const float* go = (const float*)d_in[2];
    const float* Wz = (const float*)d_in[3];
    const float* bz = (const float*)d_in[4];
    const float* Wr = (const float*)d_in[5];
    const float* br = (const float*)d_in[6];
    const float* Wh = (const float*)d_in[7];
    const float* bh = (const float*)d_in[8];
    const float* pw = (const float*)d_in[9];
    const float* pb = (const float*)d_in[10];
    const int*   ei = (const int*)d_in[11];
    float* out = (float*)d_out;

    dim3 g2(NN, 2, 2), g1(NN, 1, 2);

    // launches 1-3: setup the sacrificial gemm needs
    k_zero<<<(NN + 255) / 256, 256>>>();
    k_load_acts<<<(3 * NB * HH + 255) / 256, 256>>>(go, hs);
    k_build_wzr<<<(2 * 128 * 640 + 255) / 256, 256>>>(Wz, Wr);
    // launch 4: SACRIFICIAL pipelined gemm — lands in the ncu capture window
    // to verify the cp.async fix. Writes g_z / g_vr, fully overwritten below.
    k_gemm_zr<<<625, 256>>>(0, bz, br);
    // real CSR build
    k_degcnt<<<(EE + 255) / 256, 256>>>(ew, ei);
    k_scan<<<2, 1024>>>();
    k_fill<<<(EE + 255) / 256, 256>>>(ew, ei);
    k_pad<<<(2 * NN + 255) / 256, 256>>>();
    k_build_wh<<<(2 * 64 * 640 + 255) / 256, 256>>>(Wh);

    for (int l = 0; l < 2; l++) {
        k_prop7<<<g2, 128>>>(0, 1, l, 0, 1, 0, 2, 0, 0);   // slot1 = A_f s0; slot2 = A_r s0
        k_prop7<<<g2, 128>>>(0, 1, l, 1, 3, 2, 4, 1, 0);   // slot3/4 = 2 A(slot1/2) - s0

        k_gemm_zr<<<625, 256>>>(l, bz + l * HH, br + l * HH);

        k_prop7<<<g1, 128>>>(2, 2, l, 0, 1, 0, 2, 0, 0);
        k_prop7<<<g1, 128>>>(2, 2, l, 1, 3, 2, 4, 1, 0);

        k_gemm_h<<<625, 256>>>(l, bh + l * HH);            // -> new h in vx slot0
    }

    k_proj<<<NB / 8, 256>>>(pw, pb, out);
}

// round 17
// speedup vs baseline: 1.4223x; 1.0658x over previous
#include <cuda_runtime.h>
#include <cuda_fp16.h>

#define NN   10000
#define EE   160000
#define EEP  240000         // padded CSR capacity per dir
#define BB   8
#define HH   64
#define PART 320            // 5 slots * 64 features per (node,batch) row
#define NB   (NN*BB)        // 80000
#define VHL  (NB*PART)      // one vh layer

// ---------------- device scratch ----------------
__device__ float g_deg_out[NN];
__device__ float g_deg_in[NN];
__device__ int   g_cnt[2][NN];
__device__ int   g_off[2][NN+1];
__device__ int   g_cur[2][NN];
__device__ int   g_nbr[2][EEP];
__device__ float g_wgt[2][EEP];

__device__ __half g_vx[VHL];      // x-part slots: 0=x 1=A_f x 2=A_r x 3=cheb_f 4=cheb_r
__device__ __half g_vh[2*VHL];    // h-part slots, per layer
__device__ __half g_vr[VHL];      // (R*h)-part slots
__device__ float  g_z [NB*HH];    // Z gate (fp32)
__device__ __half g_WZR[2*128*640];  // fp16 weights, n-major [l][n][640] for Z|R gemm
__device__ __half g_WH [2*64*640];   // fp16 weights, n-major [l][n][640] for H gemm

// ---------------- helpers ----------------
struct __align__(8)  h2x2 { __half2 a, b; };
struct __align__(16) h2x4 { __half2 a, b, c, d; };

__device__ __forceinline__ float sigm(float x) { return 1.f / (1.f + __expf(-x)); }

__device__ __forceinline__ void mma_f16(float &c0, float &c1, float &c2, float &c3,
                                        unsigned a0, unsigned a1, unsigned a2, unsigned a3,
                                        unsigned b0, unsigned b1) {
    asm volatile(
        "mma.sync.aligned.m16n8k16.row.col.f32.f16.f16.f32 "
        "{%0,%1,%2,%3}, {%4,%5,%6,%7}, {%8,%9}, {%0,%1,%2,%3};"
        : "+f"(c0), "+f"(c1), "+f"(c2), "+f"(c3)
        : "r"(a0), "r"(a1), "r"(a2), "r"(a3), "r"(b0), "r"(b1));
}

__device__ __forceinline__ unsigned smem_u32(const void* p) {
    return (unsigned)__cvta_generic_to_shared(p);
}
__device__ __forceinline__ void cp16(unsigned dst, const void* src) {
    asm volatile("cp.async.cg.shared.global [%0], [%1], 16;" :: "r"(dst), "l"(src));
}
__device__ __forceinline__ void cp_commit() {
    asm volatile("cp.async.commit_group;");
}
template<int N> __device__ __forceinline__ void cp_wait() {
    asm volatile("cp.async.wait_group %0;" :: "n"(N));
}

__device__ __forceinline__ __half* partbuf(int id, int l) {
    return id == 0 ? g_vx : (id == 1 ? g_vh + l * VHL : g_vr);
}

// ---------------- setup ----------------
__global__ void k_zero() {
    int i = blockIdx.x * 256 + threadIdx.x;
    if (i >= NN) return;
    g_deg_out[i] = 0.f; g_deg_in[i] = 0.f;
    g_cnt[0][i] = 0;    g_cnt[1][i] = 0;
}

__global__ void k_degcnt(const float* __restrict__ ew, const int* __restrict__ ei) {
    int e = blockIdx.x * 256 + threadIdx.x;
    if (e >= EE) return;
    int s = ei[e], d = ei[EE + e];
    float w = ew[e];
    atomicAdd(&g_deg_out[s], w);
    atomicAdd(&g_deg_in[d],  w);
    atomicAdd(&g_cnt[0][d], 1);
    atomicAdd(&g_cnt[1][s], 1);
}

// scan with counts padded up to multiples of 8 (keeps segments 8-aligned)
__global__ void k_scan() {   // grid=2, block=1024
    int d = blockIdx.x;
    __shared__ int sums[1024];
    int t = threadIdx.x;
    const int CH = 10;
    int base = t * CH;
    int s = 0;
    for (int i = 0; i < CH; i++) {
        int idx = base + i;
        if (idx < NN) s += (g_cnt[d][idx] + 7) & ~7;
    }
    sums[t] = s; __syncthreads();
    for (int off = 1; off < 1024; off <<= 1) {
        int v = (t >= off) ? sums[t - off] : 0;
        __syncthreads();
        sums[t] += v;
        __syncthreads();
    }
    int run = (t == 0) ? 0 : sums[t - 1];
    for (int i = 0; i < CH; i++) {
        int idx = base + i;
        if (idx < NN) {
            g_off[d][idx] = run; g_cur[d][idx] = run;
            run += (g_cnt[d][idx] + 7) & ~7;
        }
    }
    if (t == 1023) g_off[d][NN] = run;
}

__global__ void k_fill(const float* __restrict__ ew, const int* __restrict__ ei) {
    int e = blockIdx.x * 256 + threadIdx.x;
    if (e >= EE) return;
    int s = ei[e], d = ei[EE + e];
    float w = ew[e];
    float wo = g_deg_out[s]; float nout = w / (wo > 0.f ? wo : 1.f);
    float wi = g_deg_in[d];  float nin  = w / (wi > 0.f ? wi : 1.f);
    int p = atomicAdd(&g_cur[0][d], 1); g_nbr[0][p] = s; g_wgt[0][p] = nout;
    int q = atomicAdd(&g_cur[1][s], 1); g_nbr[1][q] = d; g_wgt[1][q] = nin;
}

// fill padding slots with nbr=0, wgt=0 (exact zero contribution)
__global__ void k_pad() {
    int i = blockIdx.x * 256 + threadIdx.x;
    if (i >= 2 * NN) return;
    int d = i >= NN ? 1 : 0;
    int n = i - d * NN;
    int s = g_cur[d][n], e = g_off[d][n + 1];
    for (int j = s; j < e; j++) { g_nbr[d][j] = 0; g_wgt[d][j] = 0.f; }
}

// go -> vx slot0; hs (both layers) -> vh slot0
__global__ void k_load_acts(const float* __restrict__ go, const float* __restrict__ hs) {
    int t = blockIdx.x * 256 + threadIdx.x;
    if (t >= 3 * NB * HH) return;
    int seg = t / (NB * HH);
    int tt = t - seg * (NB * HH);
    int f = tt & 63; int rest = tt >> 6;
    int n = rest % NN; int b = rest / NN;
    int row = (n * BB + b) * PART + f;
    if (seg == 0) g_vx[row] = __float2half_rn(go[tt]);
    else          g_vh[(seg - 1) * VHL + row] = __float2half_rn(hs[(seg - 1) * NB * HH + tt]);
}

// W layout [L,2,K,128,64]. Slots: 0:(dir0+dir1,k0) 1:(0,k1) 2:(1,k1) 3:(0,k2) 4:(1,k2)
__device__ __forceinline__ float wslot(const float* W, int l, int s, int wrow, int o) {
    if (s == 0) {
        return W[((((l*2+0)*3+0)*128 + wrow)*64) + o] +
               W[((((l*2+1)*3+0)*128 + wrow)*64) + o];
    }
    int dir = (s == 1 || s == 3) ? 0 : 1;
    int k   = (s <= 2) ? 1 : 2;
    return W[((((l*2+dir)*3+k)*128 + wrow)*64) + o];
}

__global__ void k_build_wzr(const float* __restrict__ Wz, const float* __restrict__ Wr) {
    int idx = blockIdx.x * 256 + threadIdx.x;
    if (idx >= 2 * 128 * 640) return;
    int l = idx >= 128 * 640 ? 1 : 0;
    int li = idx - l * 128 * 640;
    int n = li / 640, j = li % 640;
    int p = j / 320, s = (j % 320) / 64, f = j & 63;
    int wrow = p * 64 + f;
    const float* W = (n < 64) ? Wz : Wr;
    g_WZR[l * 128 * 640 + n * 640 + j] = __float2half_rn(wslot(W, l, s, wrow, n & 63));
}

__global__ void k_build_wh(const float* __restrict__ Wh) {
    int idx = blockIdx.x * 256 + threadIdx.x;
    if (idx >= 2 * 64 * 640) return;
    int l = idx >= 64 * 640 ? 1 : 0;
    int li = idx - l * 64 * 640;
    int n = li / 640, j = li % 640;
    int p = j / 320, s = (j % 320) / 64, f = j & 63;
    g_WH[l * 64 * 640 + n * 640 + j] = __float2half_rn(wslot(Wh, l, s, p * 64 + f, n));
}

// ---------------- propagation v7: padded CSR + vectorized edge loads ----------------
// grid: (NN, nbuf, 2 dirs); block 128: warp = 2 batches, 16 lanes * 4 halves = 64 feats
__global__ void __launch_bounds__(128) k_prop7(int bufA, int bufB, int lvh,
                                               int s_in_f, int s_out_f,
                                               int s_in_r, int s_out_r,
                                               int cheb, int s_prev) {
    int dir = blockIdx.z;
    __half* buf = partbuf(blockIdx.y == 0 ? bufA : bufB, lvh);
    const int*   off = g_off[dir];
    const int*   nbr = g_nbr[dir];
    const float* wgt = g_wgt[dir];
    int s_in  = dir ? s_in_r  : s_in_f;
    int s_out = dir ? s_out_r : s_out_f;
    int n    = blockIdx.x;
    int w    = threadIdx.x >> 5;
    int lane = threadIdx.x & 31;
    int b    = w * 2 + (lane >> 4);
    int fo   = (lane & 15) * 4;
    int beg = off[n], end = off[n + 1];   // 8-aligned, count multiple of 8
    int boff = b * PART + s_in * 64 + fo;
    const int4*   nb4 = (const int4*)(nbr + beg);
    const float4* wg4 = (const float4*)(wgt + beg);
    int nb = (end - beg) >> 3;
    float4 acc = make_float4(0.f, 0.f, 0.f, 0.f);
    for (int i = 0; i < nb; i++) {
        int4   n0 = __ldg(&nb4[2 * i]);
        int4   n1 = __ldg(&nb4[2 * i + 1]);
        float4 w0 = __ldg(&wg4[2 * i]);
        float4 w1 = __ldg(&wg4[2 * i + 1]);
        {
            h2x2 v = *(const h2x2*)(buf + n0.x * (BB * PART) + boff);
            float2 f01 = __half22float2(v.a), f23 = __half22float2(v.b);
            acc.x += w0.x * f01.x; acc.y += w0.x * f01.y;
            acc.z += w0.x * f23.x; acc.w += w0.x * f23.y;
        }
        {
            h2x2 v = *(const h2x2*)(buf + n0.y * (BB * PART) + boff);
            float2 f01 = __half22float2(v.a), f23 = __half22float2(v.b);
            acc.x += w0.y * f01.x; acc.y += w0.y * f01.y;
            acc.z += w0.y * f23.x; acc.w += w0.y * f23.y;
        }
        {
            h2x2 v = *(const h2x2*)(buf + n0.z * (BB * PART) + boff);
            float2 f01 = __half22float2(v.a), f23 = __half22float2(v.b);
            acc.x += w0.z * f01.x; acc.y += w0.z * f01.y;
            acc.z += w0.z * f23.x; acc.w += w0.z * f23.y;
        }
        {
            h2x2 v = *(const h2x2*)(buf + n0.w * (BB * PART) + boff);
            float2 f01 = __half22float2(v.a), f23 = __half22float2(v.b);
            acc.x += w0.w * f01.x; acc.y += w0.w * f01.y;
            acc.z += w0.w * f23.x; acc.w += w0.w * f23.y;
        }
        {
            h2x2 v = *(const h2x2*)(buf + n1.x * (BB * PART) + boff);
            float2 f01 = __half22float2(v.a), f23 = __half22float2(v.b);
            acc.x += w1.x * f01.x; acc.y += w1.x * f01.y;
            acc.z += w1.x * f23.x; acc.w += w1.x * f23.y;
        }
        {
            h2x2 v = *(const h2x2*)(buf + n1.y * (BB * PART) + boff);
            float2 f01 = __half22float2(v.a), f23 = __half22float2(v.b);
            acc.x += w1.y * f01.x; acc.y += w1.y * f01.y;
            acc.z += w1.y * f23.x; acc.w += w1.y * f23.y;
        }
        {
            h2x2 v = *(const h2x2*)(buf + n1.z * (BB * PART) + boff);
            float2 f01 = __half22float2(v.a), f23 = __half22float2(v.b);
            acc.x += w1.z * f01.x; acc.y += w1.z * f01.y;
            acc.z += w1.z * f23.x; acc.w += w1.z * f23.y;
        }
        {
            h2x2 v = *(const h2x2*)(buf + n1.w * (BB * PART) + boff);
            float2 f01 = __half22float2(v.a), f23 = __half22float2(v.b);
            acc.x += w1.w * f01.x; acc.y += w1.w * f01.y;
            acc.z += w1.w * f23.x; acc.w += w1.w * f23.y;
        }
    }
    int orow = (n * BB + b) * PART;
    float4 res = acc;
    if (cheb) {
        h2x2 pv = *(const h2x2*)(buf + orow + s_prev * 64 + fo);
        float2 p01 = __half22float2(pv.a), p23 = __half22float2(pv.b);
        res.x = 2.f * acc.x - p01.x; res.y = 2.f * acc.y - p01.y;
        res.z = 2.f * acc.z - p23.x; res.w = 2.f * acc.w - p23.y;
    }
    h2x2 o;
    o.a = __floats2half2_rn(res.x, res.y);
    o.b = __floats2half2_rn(res.z, res.w);
    *(h2x2*)(buf + orow + s_out * 64 + fo) = o;
}

// ---------------- fp16 tensor-core GEMMs: 4-buffer, 3-deep cp.async, KC=16 ----------------
// Stage rows padded to 24 halves (48B): 16B-aligned cp.async dsts + conflict-free LDS.
// Z|R: [80000 x 640] @ [640 x 128]; 40 k-stages of 16
__global__ void __launch_bounds__(256) k_gemm_zr(int l,
                                                 const float* __restrict__ bz,
                                                 const float* __restrict__ br) {
    __shared__ __align__(16) __half As[4][128][24];
    __shared__ __align__(16) __half Bs[4][128][24];
    const __half* W = g_WZR + l * 128 * 640;
    const __half* vh = g_vh + l * VHL;
    int tid = threadIdx.x;
    int wid = tid >> 5, lane = tid & 31;
    int warpM = wid & 3, warpN = wid >> 2;
    int g4 = lane >> 2, t4 = lane & 3;
    int rowBase = blockIdx.x * 128;
    int ar = tid >> 1, ac8 = (tid & 1) * 8;    // per-thread A/B load coords

    float c[2][8][4];
#pragma unroll
    for (int mt = 0; mt < 2; mt++)
#pragma unroll
        for (int nt = 0; nt < 8; nt++)
#pragma unroll
            for (int i = 0; i < 4; i++) c[mt][nt][i] = 0.f;

    auto issue = [&](int kk, int buf) {
        const __half* Asrc = (kk < 20) ? g_vx : vh;
        int soff = (kk < 20 ? kk : kk - 20) * 16;
        cp16(smem_u32(&As[buf][ar][ac8]),
             Asrc + (rowBase + ar) * PART + soff + ac8);
        cp16(smem_u32(&Bs[buf][ar][ac8]), W + ar * 640 + kk * 16 + ac8);
        cp_commit();
    };

    issue(0, 0); issue(1, 1); issue(2, 2);
    for (int kk = 0; kk < 40; kk++) {
        int buf = kk & 3;
        cp_wait<2>();
        __syncthreads();
        if (kk + 3 < 40) issue(kk + 3, (kk + 3) & 3);
        else             cp_commit();
        int kA = 2 * t4;
        unsigned a[2][4];
#pragma unroll
        for (int mt = 0; mt < 2; mt++) {
            int rm = warpM * 32 + mt * 16;
            a[mt][0] = *(const unsigned*)&As[buf][rm + g4][kA];
            a[mt][1] = *(const unsigned*)&As[buf][rm + g4 + 8][kA];
            a[mt][2] = *(const unsigned*)&As[buf][rm + g4][kA + 8];
            a[mt][3] = *(const unsigned*)&As[buf][rm + g4 + 8][kA + 8];
        }
#pragma unroll
        for (int nt = 0; nt < 8; nt++) {
            int cn = warpN * 64 + nt * 8;
            unsigned b0 = *(const unsigned*)&Bs[buf][cn + g4][kA];
            unsigned b1 = *(const unsigned*)&Bs[buf][cn + g4][kA + 8];
#pragma unroll
            for (int mt = 0; mt < 2; mt++)
                mma_f16(c[mt][nt][0], c[mt][nt][1], c[mt][nt][2], c[mt][nt][3],
                        a[mt][0], a[mt][1], a[mt][2], a[mt][3], b0, b1);
        }
    }

#pragma unroll
    for (int mt = 0; mt < 2; mt++) {
#pragma unroll
        for (int nt = 0; nt < 8; nt++) {
            int gr0 = rowBase + warpM * 32 + mt * 16 + g4;
            int cv  = nt * 8 + 2 * t4;
            if (warpN == 0) {
                float bz0 = __ldg(&bz[cv]), bz1 = __ldg(&bz[cv + 1]);
                g_z[gr0 * HH + cv]           = sigm(c[mt][nt][0] + bz0);
                g_z[gr0 * HH + cv + 1]       = sigm(c[mt][nt][1] + bz1);
                g_z[(gr0 + 8) * HH + cv]     = sigm(c[mt][nt][2] + bz0);
                g_z[(gr0 + 8) * HH + cv + 1] = sigm(c[mt][nt][3] + bz1);
            } else {
                float br0 = __ldg(&br[cv]), br1 = __ldg(&br[cv + 1]);
                float h00 = __half2float(vh[gr0 * PART + cv]);
                float h01 = __half2float(vh[gr0 * PART + cv + 1]);
                float h10 = __half2float(vh[(gr0 + 8) * PART + cv]);
                float h11 = __half2float(vh[(gr0 + 8) * PART + cv + 1]);
                g_vr[gr0 * PART + cv]           = __float2half_rn(sigm(c[mt][nt][0] + br0) * h00);
                g_vr[gr0 * PART + cv + 1]       = __float2half_rn(sigm(c[mt][nt][1] + br1) * h01);
                g_vr[(gr0 + 8) * PART + cv]     = __float2half_rn(sigm(c[mt][nt][2] + br0) * h10);
                g_vr[(gr0 + 8) * PART + cv + 1] = __float2half_rn(sigm(c[mt][nt][3] + br1) * h11);
            }
        }
    }
}

// H: [80000 x 640] @ [640 x 64]; 40 k-stages of 16. GRU update -> vx slot0
__global__ void __launch_bounds__(256) k_gemm_h(int l, const float* __restrict__ bh) {
    __shared__ __align__(16) __half As[4][128][24];
    __shared__ __align__(16) __half Bs[4][64][24];
    const __half* W = g_WH + l * 64 * 640;
    const __half* vh = g_vh + l * VHL;
    int tid = threadIdx.x;
    int wid = tid >> 5, lane = tid & 31;
    int g4 = lane >> 2, t4 = lane & 3;
    int rowBase = blockIdx.x * 128;
    int ar = tid >> 1, ac8 = (tid & 1) * 8;

    float c[8][4];
#pragma unroll
    for (int nt = 0; nt < 8; nt++)
#pragma unroll
        for (int i = 0; i < 4; i++) c[nt][i] = 0.f;

    auto issue = [&](int kk, int buf) {
        const __half* Asrc = (kk < 20) ? g_vx : g_vr;
        int soff = (kk < 20 ? kk : kk - 20) * 16;
        cp16(smem_u32(&As[buf][ar][ac8]),
             Asrc + (rowBase + ar) * PART + soff + ac8);
        if (ar < 64)
            cp16(smem_u32(&Bs[buf][ar][ac8]), W + ar * 640 + kk * 16 + ac8);
        cp_commit();
    };

    issue(0, 0); issue(1, 1); issue(2, 2);
    for (int kk = 0; kk < 40; kk++) {
        int buf = kk & 3;
        cp_wait<2>();
        __syncthreads();
        if (kk + 3 < 40) issue(kk + 3, (kk + 3) & 3);
        else             cp_commit();
        int kA = 2 * t4;
        int rm = wid * 16;
        unsigned a0 = *(const unsigned*)&As[buf][rm + g4][kA];
        unsigned a1 = *(const unsigned*)&As[buf][rm + g4 + 8][kA];
        unsigned a2 = *(const unsigned*)&As[buf][rm + g4][kA + 8];
        unsigned a3 = *(const unsigned*)&As[buf][rm + g4 + 8][kA + 8];
#pragma unroll
        for (int nt = 0; nt < 8; nt++) {
            unsigned b0 = *(const unsigned*)&Bs[buf][nt * 8 + g4][kA];
            unsigned b1 = *(const unsigned*)&Bs[buf][nt * 8 + g4][kA + 8];
            mma_f16(c[nt][0], c[nt][1], c[nt][2], c[nt][3], a0, a1, a2, a3, b0, b1);
        }
    }

#pragma unroll
    for (int nt = 0; nt < 8; nt++) {
        int gr0 = rowBase + wid * 16 + g4;
        int cv  = nt * 8 + 2 * t4;
        float bh0 = __ldg(&bh[cv]), bh1 = __ldg(&bh[cv + 1]);
#pragma unroll
        for (int half_i = 0; half_i < 2; half_i++) {
            int gr = gr0 + half_i * 8;
            float ht0 = tanhf(c[nt][half_i * 2 + 0] + bh0);
            float ht1 = tanhf(c[nt][half_i * 2 + 1] + bh1);
            float z0 = g_z[gr * HH + cv], z1 = g_z[gr * HH + cv + 1];
            float h0 = __half2float(vh[gr * PART + cv]);
            float h1 = __half2float(vh[gr * PART + cv + 1]);
            g_vx[gr * PART + cv]     = __float2half_rn(z0 * h0 + (1.f - z0) * ht0);
            g_vx[gr * PART + cv + 1] = __float2half_rn(z1 * h1 + (1.f - z1) * ht1);
        }
    }
}

// ---------------- projection ----------------
__global__ void __launch_bounds__(256) k_proj(const float* __restrict__ pw,
                                              const float* __restrict__ pb,
                                              float* __restrict__ out) {
    __shared__ float Ws[64 * 32];
    __shared__ float Bsh[32];
    int tid = threadIdx.x;
    for (int i = tid; i < 64 * 32; i += 256) Ws[i] = pw[i];
    if (tid < 32) Bsh[tid] = pb[tid];
    __syncthreads();
    int w = tid >> 5, lane = tid & 31;
    int g = blockIdx.x * 8 + w;
    const __half* x = g_vx + g * PART;
    float xv0 = __half2float(x[lane]);
    float xv1 = __half2float(x[32 + lane]);
    float acc = Bsh[lane];
#pragma unroll
    for (int f = 0; f < 32; f++)
        acc += __shfl_sync(0xffffffffu, xv0, f) * Ws[f * 32 + lane];
#pragma unroll
    for (int f = 0; f < 32; f++)
        acc += __shfl_sync(0xffffffffu, xv1, f) * Ws[(32 + f) * 32 + lane];
    int n = g >> 3, b = g & 7;
    out[(b * NN + n) * 32 + lane] = acc;
}

// ---------------- launch ----------------
extern "C" void kernel_launch(void* const* d_in, const int* in_sizes, int n_in,
                              void* d_out, int out_size) {
    (void)in_sizes; (void)n_in; (void)out_size;
    const float* ew = (const float*)d_in[0];
    const float* hs = (const float*)d_in[1];
    const float* go = (const float*)d_in[2];
    const float* Wz = (const float*)d_in[3];
    const float* bz = (const float*)d_in[4];
    const float* Wr = (const float*)d_in[5];
    const float* br = (const float*)d_in[6];
    const float* Wh = (const float*)d_in[7];
    const float* bh = (const float*)d_in[8];
    const float* pw = (const float*)d_in[9];
    const float* pb = (const float*)d_in[10];
    const int*   ei = (const int*)d_in[11];
    float* out = (float*)d_out;

    dim3 g2(NN, 2, 2), g1(NN, 1, 2);

    k_zero<<<(NN + 255) / 256, 256>>>();
    k_degcnt<<<(EE + 255) / 256, 256>>>(ew, ei);
    k_scan<<<2, 1024>>>();
    k_fill<<<(EE + 255) / 256, 256>>>(ew, ei);
    k_pad<<<(2 * NN + 255) / 256, 256>>>();
    k_load_acts<<<(3 * NB * HH + 255) / 256, 256>>>(go, hs);
    k_build_wzr<<<(2 * 128 * 640 + 255) / 256, 256>>>(Wz, Wr);
    k_build_wh<<<(2 * 64 * 640 + 255) / 256, 256>>>(Wh);

    for (int l = 0; l < 2; l++) {
        k_prop7<<<g2, 128>>>(0, 1, l, 0, 1, 0, 2, 0, 0);   // slot1 = A_f s0; slot2 = A_r s0
        k_prop7<<<g2, 128>>>(0, 1, l, 1, 3, 2, 4, 1, 0);   // slot3/4 = 2 A(slot1/2) - s0

        k_gemm_zr<<<625, 256>>>(l, bz + l * HH, br + l * HH);

        k_prop7<<<g1, 128>>>(2, 2, l, 0, 1, 0, 2, 0, 0);
        k_prop7<<<g1, 128>>>(2, 2, l, 1, 3, 2, 4, 1, 0);

        k_gemm_h<<<625, 256>>>(l, bh + l * HH);            // -> new h in vx slot0
    }

    k_proj<<<NB / 8, 256>>>(pw, pb, out);
}